// round 11
// baseline (speedup 1.0000x reference)
#include <cuda_runtime.h>
#include <cuda_fp16.h>

#define NN 100000
#define NE 1600000
#define NG 256
#define HID 64

// ---- static scratch (no allocations allowed) ----
__device__ __align__(16) __half g_xwA[NN * HID];   // fp16 transformed features (ping)
__device__ __align__(16) __half g_xwB[NN * HID];   // fp16 transformed features (pong)
__device__ unsigned long long g_packed[NN];        // [40:64)=in-degree count, [0:40)=sum(w) Q24
__device__ float g_deg[NN];                        // dinv = rsqrt(deg)
__device__ int   g_row[NN + 1];                    // CSR row offsets (by dst)
__device__ __align__(8) int2 g_nodeinfo[NN];       // (row offset, dinv-as-bits) packed
__device__ int   g_rank[NE];                       // per-edge rank within its dst bucket
__device__ unsigned long long g_lbpack[128];       // lookback: [32:64)=flag, [0:32)=block total
__device__ __align__(16) int2 g_edge[NE];          // CSR record: (src, norm-as-bits)
__device__ float g_sums[NG];
__device__ float g_cnt[NG];

#define Q24 16777216.0f

// -------------------- single packed atomic: deg + hist + rank --------------------
// (g_packed was zeroed by k_scan of the previous launch; zero at module load initially)
__global__ void k_deg_hist(const int* __restrict__ dst, const float* __restrict__ w, int E) {
    int e = blockIdx.x * blockDim.x + threadIdx.x;
    if (e < E) {
        int d = dst[e];
        unsigned long long add =
            (1ull << 40) | (unsigned long long)__float2uint_rn(w[e] * Q24);
        unsigned long long old = atomicAdd(&g_packed[d], add);
        g_rank[e] = (int)(old >> 40);
    }
}

// -------------------- single-pass decoupled-lookback scan --------------------
// 98 blocks x 1024 threads: all blocks resident simultaneously (98 < #SMs),
// so the lookback spin cannot deadlock. Produces g_row, g_nodeinfo, g_deg.
// Also re-zeroes g_packed for the next launch (consumed only here).
__global__ __launch_bounds__(1024) void k_scan(int n, int E) {
    __shared__ int ws[32];
    __shared__ int prefix_s;
    int b = blockIdx.x, t = threadIdx.x;
    int i = b * 1024 + t;
    unsigned long long pk = (i < n) ? g_packed[i] : 0ull;
    int v = (int)(pk >> 40);
    if (i < n) g_packed[i] = 0ull;          // reset for next launch

    const unsigned full = 0xffffffffu;
    int lane = t & 31, warp = t >> 5;
    int x = v;
    #pragma unroll
    for (int off = 1; off < 32; off <<= 1) {
        int y = __shfl_up_sync(full, x, off);
        if (lane >= off) x += y;
    }
    if (lane == 31) ws[warp] = x;
    __syncthreads();
    if (warp == 0) {
        int y = ws[lane];
        #pragma unroll
        for (int off = 1; off < 32; off <<= 1) {
            int z = __shfl_up_sync(full, y, off);
            if (lane >= off) y += z;
        }
        ws[lane] = y;
    }
    __syncthreads();
    int blockpref = (warp > 0) ? ws[warp - 1] : 0;
    int incl = x + blockpref;

    // publish this block's total (flag in high word; single 64-bit store)
    if (t == 1023) {
        unsigned long long p = (1ull << 32) | (unsigned)incl;
        *((volatile unsigned long long*)&g_lbpack[b]) = p;
    }

    // lookback: sum totals of all predecessor blocks
    if (t == 0) prefix_s = 0;
    __syncthreads();
    if (t < b) {
        unsigned long long p;
        do { p = *((volatile unsigned long long*)&g_lbpack[t]); } while (!(p >> 32));
        atomicAdd(&prefix_s, (int)(unsigned)p);
    }
    __syncthreads();

    int excl = incl - v + prefix_s;
    if (i < n) {
        g_row[i] = excl;
        float deg = 1.0f + (float)(pk & 0xFFFFFFFFFFull) * (1.0f / Q24);
        float dinv = rsqrtf(deg);
        g_deg[i] = dinv;
        int2 ni; ni.x = excl; ni.y = __float_as_int(dinv);
        g_nodeinfo[i] = ni;
    }
    if (i == n) g_row[n] = E;
}

// -------------------- merged: CSR fill (blocks >= gemm_blocks) + layer-0 GEMM --------------------
// The two halves are independent: fill consumes scan output, gemm0 consumes x/W0.
// Merging overlaps fill's L2-op-bound traffic with gemm0's FMA work.
__global__ __launch_bounds__(256) void k_fill_gemm0(
    const int* __restrict__ src, const int* __restrict__ dst,
    const float* __restrict__ w, int E,
    const float* __restrict__ X, const float* __restrict__ W, int n,
    int gemm_blocks)
{
    __shared__ float Ws[64 * 64];
    __shared__ float Xs[64 * 65];

    int tid = threadIdx.x;

    if (blockIdx.x >= gemm_blocks) {
        // ---- fill part ----
        int e = (blockIdx.x - gemm_blocks) * 256 + tid;
        if (e < E) {
            int s = src[e], d = dst[e];
            int2 di = __ldg(g_nodeinfo + d);           // one 8B gather: (row, dinv)
            float nv = __ldg(g_deg + s) * w[e] * __int_as_float(di.y);
            int pos = di.x + g_rank[e];
            int2 rec; rec.x = s; rec.y = __float_as_int(nv);
            g_edge[pos] = rec;
        }
        return;
    }

    // ---- gemm0 part: xwA = X @ W0 (fp16 out) ----
    int row0 = blockIdx.x * 64;

    const float4* W4 = (const float4*)W;
    float4* Ws4 = (float4*)Ws;
    #pragma unroll
    for (int i = 0; i < 4; i++) Ws4[tid + 256 * i] = W4[tid + 256 * i];

    const float4* X4 = (const float4*)(X + (size_t)row0 * 64);
    #pragma unroll
    for (int i = 0; i < 4; i++) {
        int idx = tid + 256 * i;
        int r = idx >> 4, c4 = idx & 15;
        if (row0 + r < n) {
            float4 v = X4[idx];
            float* p = &Xs[r * 65 + c4 * 4];
            p[0] = v.x; p[1] = v.y; p[2] = v.z; p[3] = v.w;
        }
    }
    __syncthreads();

    int r = tid >> 2;
    int cs = (tid & 3) * 16;
    int row = row0 + r;
    if (row >= n) return;

    float acc[16];
    #pragma unroll
    for (int c = 0; c < 16; c++) acc[c] = 0.f;
    #pragma unroll
    for (int k = 0; k < 64; k++) {
        float xv = Xs[r * 65 + k];
        const float4* wr = (const float4*)&Ws[k * 64 + cs];
        #pragma unroll
        for (int c4 = 0; c4 < 4; c4++) {
            float4 wv = wr[c4];
            acc[c4 * 4 + 0] += xv * wv.x;
            acc[c4 * 4 + 1] += xv * wv.y;
            acc[c4 * 4 + 2] += xv * wv.z;
            acc[c4 * 4 + 3] += xv * wv.w;
        }
    }

    __half2 hh[8];
    #pragma unroll
    for (int i = 0; i < 8; i++) hh[i] = __floats2half2_rn(acc[2 * i], acc[2 * i + 1]);
    uint4* dstp = (uint4*)(g_xwA + (size_t)row * 64 + cs);
    dstp[0] = ((uint4*)hh)[0];
    dstp[1] = ((uint4*)hh)[1];
}

// ---- gather core: 8 threads/node, each accumulates 8 features in fp32 ----
// Lane j reads uint4 slot j of each gathered row: warp covers full 128B rows.
#define ACC8v(v, nv) { const __half2* _h = (const __half2*)&(v); \
    float2 _t0 = __half22float2(_h[0]), _t1 = __half22float2(_h[1]); \
    float2 _t2 = __half22float2(_h[2]), _t3 = __half22float2(_h[3]); \
    a[0] += _t0.x * (nv); a[1] += _t0.y * (nv); \
    a[2] += _t1.x * (nv); a[3] += _t1.y * (nv); \
    a[4] += _t2.x * (nv); a[5] += _t2.y * (nv); \
    a[6] += _t3.x * (nv); a[7] += _t3.y * (nv); }

__device__ __forceinline__ void gather_core8(const __half* __restrict__ xwh,
                                             int node, int j,
                                             const float* __restrict__ bias,
                                             float* a /*[8]*/)
{
    int2 ni = __ldg(g_nodeinfo + node);      // (start, dinv)
    int start = ni.x;
    int end   = __ldg(g_row + node + 1);
    float dv = __int_as_float(ni.y);
    float inv = dv * dv;

    const uint4* xw = (const uint4*)xwh;     // 8 slots of 8 halfs per row

    // bias + self-loop
    {
        uint4 v = __ldg(&xw[(size_t)node * 8 + j]);
        const float4* b4 = (const float4*)(bias + j * 8);
        float4 b0 = __ldg(b4), b1 = __ldg(b4 + 1);
        #pragma unroll
        for (int q = 0; q < 8; q++) a[q] = 0.f;
        ACC8v(v, inv);
        a[0] += b0.x; a[1] += b0.y; a[2] += b0.z; a[3] += b0.w;
        a[4] += b1.x; a[5] += b1.y; a[6] += b1.z; a[7] += b1.w;
    }

    int e = start;
    for (; e + 3 < end; e += 4) {
        int2 p0 = __ldg(g_edge + e);
        int2 p1 = __ldg(g_edge + e + 1);
        int2 p2 = __ldg(g_edge + e + 2);
        int2 p3 = __ldg(g_edge + e + 3);
        uint4 u0 = __ldg(&xw[(size_t)p0.x * 8 + j]);
        uint4 u1 = __ldg(&xw[(size_t)p1.x * 8 + j]);
        uint4 u2 = __ldg(&xw[(size_t)p2.x * 8 + j]);
        uint4 u3 = __ldg(&xw[(size_t)p3.x * 8 + j]);
        float n0 = __int_as_float(p0.y);
        float n1 = __int_as_float(p1.y);
        float n2 = __int_as_float(p2.y);
        float n3 = __int_as_float(p3.y);
        ACC8v(u0, n0); ACC8v(u1, n1); ACC8v(u2, n2); ACC8v(u3, n3);
    }
    for (; e < end; e++) {
        int2 p0 = __ldg(g_edge + e);
        uint4 u0 = __ldg(&xw[(size_t)p0.x * 8 + j]);
        float n0 = __int_as_float(p0.y);
        ACC8v(u0, n0);
    }
}

// -------------------- fused: gather(prev) + bias -> relu -> @Wnext -> xw(next) --------------------
// 512 threads = 64 nodes x 8 threads
__global__ __launch_bounds__(512) void k_fused(
    const float* __restrict__ bias, const float* __restrict__ W,
    int in_is_A, int n)
{
    __shared__ float Ws[64 * 64];
    __shared__ float Xs[64 * 65];

    const __half* xin = in_is_A ? g_xwA : g_xwB;
    __half* xout      = in_is_A ? g_xwB : g_xwA;

    int tid = threadIdx.x;
    int row0 = blockIdx.x * 64;

    const float4* W4 = (const float4*)W;
    float4* Ws4 = (float4*)Ws;
    #pragma unroll
    for (int i = 0; i < 2; i++) Ws4[tid + 512 * i] = W4[tid + 512 * i];

    int node_l = tid >> 3;
    int j = tid & 7;
    int node = row0 + node_l;

    if (node < n) {
        float a[8];
        gather_core8(xin, node, j, bias, a);
        float* p = &Xs[node_l * 65 + j * 8];
        #pragma unroll
        for (int q = 0; q < 8; q++) p[q] = fmaxf(a[q], 0.f);   // relu for next layer input
    }
    __syncthreads();

    if (node >= n) return;
    int c0 = j * 8;

    float acc[8];
    #pragma unroll
    for (int c = 0; c < 8; c++) acc[c] = 0.f;
    #pragma unroll
    for (int k = 0; k < 64; k++) {
        float xv = Xs[node_l * 65 + k];
        const float4 w0 = *(const float4*)&Ws[k * 64 + c0];
        const float4 w1 = *(const float4*)&Ws[k * 64 + c0 + 4];
        acc[0] += xv * w0.x; acc[1] += xv * w0.y; acc[2] += xv * w0.z; acc[3] += xv * w0.w;
        acc[4] += xv * w1.x; acc[5] += xv * w1.y; acc[6] += xv * w1.z; acc[7] += xv * w1.w;
    }

    __half2 hh[4];
    #pragma unroll
    for (int i = 0; i < 4; i++) hh[i] = __floats2half2_rn(acc[2 * i], acc[2 * i + 1]);
    *(uint4*)(xout + (size_t)node * 64 + c0) = *(uint4*)hh;
}

// -------------------- fused final gather + MLP readout + pooling --------------------
// 512 threads = 64 nodes x 8 threads; reads g_xwA (layer-2 xw)
__global__ __launch_bounds__(512) void k_gather_readout(
    const float* __restrict__ bias,
    const float* __restrict__ Wr0, const float* __restrict__ br0,
    const float* __restrict__ Wr1, const float* __restrict__ br1,
    const int* __restrict__ batch, int n)
{
    __shared__ float aggS[64 * 65];
    __shared__ float W0s[64 * 32];
    __shared__ float W1s[32];
    __shared__ float b0s[32];

    int tid = threadIdx.x;
    for (int i = tid; i < 2048; i += 512) W0s[i] = Wr0[i];
    if (tid < 32) { W1s[tid] = Wr1[tid]; b0s[tid] = br0[tid]; }

    int node_l = tid >> 3;
    int j = tid & 7;
    int node = blockIdx.x * 64 + node_l;
    bool valid = (node < n);

    if (valid) {
        float a[8];
        gather_core8(g_xwA, node, j, bias, a);   // no relu on last GNN layer
        float* p = &aggS[node_l * 65 + j * 8];
        #pragma unroll
        for (int q = 0; q < 8; q++) p[q] = a[q];
    }
    __syncthreads();

    float s = 0.f, cv = 0.f;
    int g = -1;
    if (valid) {
        int c0 = j * 4;                          // 8 threads x 4 hidden cols = 32
        float acc[4];
        #pragma unroll
        for (int q = 0; q < 4; q++) acc[q] = b0s[c0 + q];
        const float* row = &aggS[node_l * 65];
        #pragma unroll
        for (int k = 0; k < 64; k++) {
            float v = row[k];
            const float4 w0 = *(const float4*)&W0s[k * 32 + c0];
            acc[0] += v * w0.x; acc[1] += v * w0.y; acc[2] += v * w0.z; acc[3] += v * w0.w;
        }
        const float4 w1 = *(const float4*)&W1s[c0];
        s = fmaxf(acc[0], 0.f) * w1.x + fmaxf(acc[1], 0.f) * w1.y
          + fmaxf(acc[2], 0.f) * w1.z + fmaxf(acc[3], 0.f) * w1.w;
        g = __ldg(batch + node);   // ALL 8 lanes of a node keep g (run contiguity)
    }

    // sum the 8 partials of each node (aligned 8-lane groups)
    const unsigned full = 0xffffffffu;
    s += __shfl_xor_sync(full, s, 4);
    s += __shfl_xor_sync(full, s, 2);
    s += __shfl_xor_sync(full, s, 1);

    if (valid && j == 0) { s += __ldg(br1); cv = 1.f; }
    else { s = 0.f; cv = 0.f; }

    // warp segmented scan over contiguous equal-g runs (4 nodes per warp,
    // natural node order -> batch sorted -> long contiguous segments)
    int lane = tid & 31;
    #pragma unroll
    for (int off = 1; off < 32; off <<= 1) {
        float so = __shfl_up_sync(full, s, off);
        float co = __shfl_up_sync(full, cv, off);
        int go = __shfl_up_sync(full, g, off);
        if (lane >= off && go == g) { s += so; cv += co; }
    }
    int gn = __shfl_down_sync(full, g, 1);
    if ((lane == 31 || gn != g) && g >= 0) {
        atomicAdd(&g_sums[g], s);
        atomicAdd(&g_cnt[g], cv);
    }
}

// finalize output + reset accumulators/lookback state for the next launch
__global__ void k_finalize(float* __restrict__ out) {
    int g = threadIdx.x;
    out[g] = g_sums[g] / fmaxf(g_cnt[g], 1.0f);
    g_sums[g] = 0.f;
    g_cnt[g] = 0.f;
    if (g < 128) g_lbpack[g] = 0ull;
}

// -------------------- launch --------------------
extern "C" void kernel_launch(void* const* d_in, const int* in_sizes, int n_in,
                              void* d_out, int out_size)
{
    const float* x   = (const float*)d_in[0];
    const int*   ei  = (const int*)d_in[1];
    const float* ew  = (const float*)d_in[2];
    const int* batch = (const int*)d_in[3];
    const float* W0  = (const float*)d_in[4];
    const float* b0  = (const float*)d_in[5];
    const float* W1  = (const float*)d_in[6];
    const float* b1  = (const float*)d_in[7];
    const float* W2  = (const float*)d_in[8];
    const float* b2  = (const float*)d_in[9];
    const float* Wr0 = (const float*)d_in[10];
    const float* br0 = (const float*)d_in[11];
    const float* Wr1 = (const float*)d_in[12];
    const float* br1 = (const float*)d_in[13];
    float* out = (float*)d_out;

    int n = in_sizes[0] / HID;       // 100000
    int E = in_sizes[2];             // 1600000
    const int* src = ei;
    const int* dst = ei + E;

    int nb = (n + 1023) / 1024;      // 98 blocks: all resident -> lookback safe
    int gb = (n + 63) / 64;          // 1563 gemm/gather blocks
    int fb = (E + 255) / 256;        // 6250 fill blocks

    // launch order: #3 (0-indexed) is k_fused -> that's what ncu captures
    k_deg_hist<<<(E + 255) / 256, 256>>>(dst, ew, E);                   // 0
    k_scan<<<nb, 1024>>>(n, E);                                         // 1
    k_fill_gemm0<<<gb + fb, 256>>>(src, dst, ew, E, x, W0, n, gb);      // 2
    k_fused<<<gb, 512>>>(b0, W1, 1, n);                                 // 3  <- profiled
    k_fused<<<gb, 512>>>(b1, W2, 0, n);                                 // 4
    k_gather_readout<<<gb, 512>>>(b2, Wr0, br0, Wr1, br1, batch, n);    // 5
    k_finalize<<<1, 256>>>(out);                                        // 6
}

// round 12
// speedup vs baseline: 2.2610x; 2.2610x over previous
#include <cuda_runtime.h>
#include <cuda_fp16.h>
#include <mma.h>
using namespace nvcuda;

#define NN 100000
#define NE 1600000
#define NG 256
#define HID 64

// ---- static scratch (no allocations allowed) ----
__device__ __align__(16) __half g_xwA[NN * HID];   // fp16 transformed features (ping)
__device__ __align__(16) __half g_xwB[NN * HID];   // fp16 transformed features (pong)
__device__ unsigned long long g_packed[NN];        // [40:64)=count, [0:40)=sum(w) Q24
__device__ float g_deg[NN];                        // dinv = rsqrt(deg)
__device__ int   g_row[NN + 1];                    // CSR row offsets (by dst)
__device__ __align__(8) int2 g_nodeinfo[NN];       // (row offset, dinv-as-bits)
__device__ int   g_rank[NE];                       // per-edge rank within dst bucket
__device__ unsigned long long g_lbpack[128];       // lookback state
__device__ __align__(16) int2 g_edge[NE];          // CSR record: (src, norm-as-bits)
__device__ float g_sums[NG];
__device__ float g_cnt[NG];

#define Q24 16777216.0f

// strides (elements) chosen for alignment + conflict avoidance
#define SA 72   // half matrix stride (mult of 8; 144B rows)
#define SC 68   // float C stride (mult of 4)
#define SB2 40  // readout B stride (32 cols + pad)
#define SC2 36  // readout C stride

// -------------------- deg + hist + rank (one packed 64b atomic) --------------------
__global__ void k_deg_hist(const int* __restrict__ dst, const float* __restrict__ w, int E) {
    int e = blockIdx.x * blockDim.x + threadIdx.x;
    if (e < E) {
        int d = dst[e];
        unsigned long long add =
            (1ull << 40) | (unsigned long long)__float2uint_rn(w[e] * Q24);
        unsigned long long old = atomicAdd(&g_packed[d], add);
        g_rank[e] = (int)(old >> 40);
    }
}

// -------------------- single-pass decoupled-lookback scan --------------------
__global__ __launch_bounds__(1024) void k_scan(int n, int E) {
    __shared__ int ws[32];
    __shared__ int prefix_s;
    int b = blockIdx.x, t = threadIdx.x;
    int i = b * 1024 + t;
    unsigned long long pk = (i < n) ? g_packed[i] : 0ull;
    int v = (int)(pk >> 40);
    if (i < n) g_packed[i] = 0ull;          // reset for next launch

    const unsigned full = 0xffffffffu;
    int lane = t & 31, warp = t >> 5;
    int x = v;
    #pragma unroll
    for (int off = 1; off < 32; off <<= 1) {
        int y = __shfl_up_sync(full, x, off);
        if (lane >= off) x += y;
    }
    if (lane == 31) ws[warp] = x;
    __syncthreads();
    if (warp == 0) {
        int y = ws[lane];
        #pragma unroll
        for (int off = 1; off < 32; off <<= 1) {
            int z = __shfl_up_sync(full, y, off);
            if (lane >= off) y += z;
        }
        ws[lane] = y;
    }
    __syncthreads();
    int blockpref = (warp > 0) ? ws[warp - 1] : 0;
    int incl = x + blockpref;

    if (t == 1023) {
        unsigned long long p = (1ull << 32) | (unsigned)incl;
        *((volatile unsigned long long*)&g_lbpack[b]) = p;
    }
    if (t == 0) prefix_s = 0;
    __syncthreads();
    if (t < b) {
        unsigned long long p;
        do { p = *((volatile unsigned long long*)&g_lbpack[t]); } while (!(p >> 32));
        atomicAdd(&prefix_s, (int)(unsigned)p);
    }
    __syncthreads();

    int excl = incl - v + prefix_s;
    if (i < n) {
        g_row[i] = excl;
        float deg = 1.0f + (float)(pk & 0xFFFFFFFFFFull) * (1.0f / Q24);
        float dinv = rsqrtf(deg);
        g_deg[i] = dinv;
        int2 ni; ni.x = excl; ni.y = __float_as_int(dinv);
        g_nodeinfo[i] = ni;
    }
    if (i == n) g_row[n] = E;
}

// -------------------- merged: CSR fill + layer-0 GEMM (wmma) --------------------
__global__ __launch_bounds__(256) void k_fill_gemm0(
    const int* __restrict__ src, const int* __restrict__ dst,
    const float* __restrict__ w, int E,
    const float* __restrict__ X, const float* __restrict__ W, int n,
    int gemm_blocks)
{
    __shared__ __half WsH[64 * SA];
    __shared__ __half XsH[64 * SA];
    __shared__ float Cs[64 * SC];

    int tid = threadIdx.x;

    if (blockIdx.x >= gemm_blocks) {
        // ---- fill part ----
        int e = (blockIdx.x - gemm_blocks) * 256 + tid;
        if (e < E) {
            int s = src[e], d = dst[e];
            int2 di = __ldg(g_nodeinfo + d);
            float nv = __ldg(g_deg + s) * w[e] * __int_as_float(di.y);
            int pos = di.x + g_rank[e];
            int2 rec; rec.x = s; rec.y = __float_as_int(nv);
            g_edge[pos] = rec;
        }
        return;
    }

    // ---- gemm0: xwA = X @ W0 via wmma ----
    int row0 = blockIdx.x * 64;

    const float4* W4 = (const float4*)W;
    #pragma unroll
    for (int i = 0; i < 4; i++) {
        int idx = tid + 256 * i;               // float4 index: k=idx>>4, c4=idx&15
        float4 f = W4[idx];
        int k = idx >> 4, c4 = idx & 15;
        __half2 h0 = __floats2half2_rn(f.x, f.y);
        __half2 h1 = __floats2half2_rn(f.z, f.w);
        uint2 u; u.x = *(unsigned*)&h0; u.y = *(unsigned*)&h1;
        *(uint2*)&WsH[k * SA + c4 * 4] = u;
    }
    const float4* X4 = (const float4*)(X + (size_t)row0 * 64);
    #pragma unroll
    for (int i = 0; i < 4; i++) {
        int idx = tid + 256 * i;
        int r = idx >> 4, c4 = idx & 15;
        if (row0 + r < n) {
            float4 f = X4[idx];
            __half2 h0 = __floats2half2_rn(f.x, f.y);
            __half2 h1 = __floats2half2_rn(f.z, f.w);
            uint2 u; u.x = *(unsigned*)&h0; u.y = *(unsigned*)&h1;
            *(uint2*)&XsH[r * SA + c4 * 4] = u;
        }
    }
    __syncthreads();

    // 8 warps x 2 tiles (tile_r = w&3, tile_c = (w>>2)*2 + t2)
    int wp = tid >> 5;
    int tile_r = wp & 3;
    #pragma unroll
    for (int t2 = 0; t2 < 2; t2++) {
        int tile_c = (wp >> 2) * 2 + t2;
        wmma::fragment<wmma::accumulator, 16, 16, 16, float> cf;
        wmma::fill_fragment(cf, 0.f);
        #pragma unroll
        for (int kk = 0; kk < 4; kk++) {
            wmma::fragment<wmma::matrix_a, 16, 16, 16, __half, wmma::row_major> af;
            wmma::fragment<wmma::matrix_b, 16, 16, 16, __half, wmma::row_major> bf;
            wmma::load_matrix_sync(af, XsH + tile_r * 16 * SA + kk * 16, SA);
            wmma::load_matrix_sync(bf, WsH + kk * 16 * SA + tile_c * 16, SA);
            wmma::mma_sync(cf, af, bf, cf);
        }
        wmma::store_matrix_sync(Cs + tile_r * 16 * SC + tile_c * 16, cf, SC, wmma::mem_row_major);
    }
    __syncthreads();

    // write fp16 out: 256 threads x 16 halves
    int r = tid >> 2, c0 = (tid & 3) * 16;
    int row = row0 + r;
    if (row >= n) return;
    const float* crow = &Cs[r * SC + c0];
    __half2 hh[8];
    #pragma unroll
    for (int i = 0; i < 8; i++) hh[i] = __floats2half2_rn(crow[2 * i], crow[2 * i + 1]);
    uint4* dstp = (uint4*)(g_xwA + (size_t)row * 64 + c0);
    dstp[0] = ((uint4*)hh)[0];
    dstp[1] = ((uint4*)hh)[1];
}

// ---- gather core: 8 threads/node, each accumulates 8 features in fp32 ----
#define ACC8v(v, nv) { const __half2* _h = (const __half2*)&(v); \
    float2 _t0 = __half22float2(_h[0]), _t1 = __half22float2(_h[1]); \
    float2 _t2 = __half22float2(_h[2]), _t3 = __half22float2(_h[3]); \
    a[0] += _t0.x * (nv); a[1] += _t0.y * (nv); \
    a[2] += _t1.x * (nv); a[3] += _t1.y * (nv); \
    a[4] += _t2.x * (nv); a[5] += _t2.y * (nv); \
    a[6] += _t3.x * (nv); a[7] += _t3.y * (nv); }

__device__ __forceinline__ void gather_core8(const __half* __restrict__ xwh,
                                             int node, int j,
                                             const float* __restrict__ bias,
                                             float* a /*[8]*/)
{
    int2 ni = __ldg(g_nodeinfo + node);
    int start = ni.x;
    int end   = __ldg(g_row + node + 1);
    float dv = __int_as_float(ni.y);
    float inv = dv * dv;

    const uint4* xw = (const uint4*)xwh;

    {
        uint4 v = __ldg(&xw[(size_t)node * 8 + j]);
        const float4* b4 = (const float4*)(bias + j * 8);
        float4 b0 = __ldg(b4), b1 = __ldg(b4 + 1);
        #pragma unroll
        for (int q = 0; q < 8; q++) a[q] = 0.f;
        ACC8v(v, inv);
        a[0] += b0.x; a[1] += b0.y; a[2] += b0.z; a[3] += b0.w;
        a[4] += b1.x; a[5] += b1.y; a[6] += b1.z; a[7] += b1.w;
    }

    int e = start;
    for (; e + 3 < end; e += 4) {
        int2 p0 = __ldg(g_edge + e);
        int2 p1 = __ldg(g_edge + e + 1);
        int2 p2 = __ldg(g_edge + e + 2);
        int2 p3 = __ldg(g_edge + e + 3);
        uint4 u0 = __ldg(&xw[(size_t)p0.x * 8 + j]);
        uint4 u1 = __ldg(&xw[(size_t)p1.x * 8 + j]);
        uint4 u2 = __ldg(&xw[(size_t)p2.x * 8 + j]);
        uint4 u3 = __ldg(&xw[(size_t)p3.x * 8 + j]);
        float n0 = __int_as_float(p0.y);
        float n1 = __int_as_float(p1.y);
        float n2 = __int_as_float(p2.y);
        float n3 = __int_as_float(p3.y);
        ACC8v(u0, n0); ACC8v(u1, n1); ACC8v(u2, n2); ACC8v(u3, n3);
    }
    for (; e < end; e++) {
        int2 p0 = __ldg(g_edge + e);
        uint4 u0 = __ldg(&xw[(size_t)p0.x * 8 + j]);
        float n0 = __int_as_float(p0.y);
        ACC8v(u0, n0);
    }
}

// -------------------- fused: gather -> relu(fp16 smem) -> wmma @W -> xw out --------------------
// 512 threads = 64 nodes x 8 threads; 16 warps = 16 wmma tiles
__global__ __launch_bounds__(512) void k_fused(
    const float* __restrict__ bias, const float* __restrict__ W,
    int in_is_A, int n)
{
    __shared__ __half WsH[64 * SA];
    __shared__ __half XsH[64 * SA];
    __shared__ float Cs[64 * SC];

    const __half* xin = in_is_A ? g_xwA : g_xwB;
    __half* xout      = in_is_A ? g_xwB : g_xwA;

    int tid = threadIdx.x;
    int row0 = blockIdx.x * 64;

    const float4* W4 = (const float4*)W;
    #pragma unroll
    for (int i = 0; i < 2; i++) {
        int idx = tid + 512 * i;
        float4 f = W4[idx];
        int k = idx >> 4, c4 = idx & 15;
        __half2 h0 = __floats2half2_rn(f.x, f.y);
        __half2 h1 = __floats2half2_rn(f.z, f.w);
        uint2 u; u.x = *(unsigned*)&h0; u.y = *(unsigned*)&h1;
        *(uint2*)&WsH[k * SA + c4 * 4] = u;
    }

    int node_l = tid >> 3;
    int j = tid & 7;
    int node = row0 + node_l;

    if (node < n) {
        float a[8];
        gather_core8(xin, node, j, bias, a);
        __half2 hh[4];
        #pragma unroll
        for (int q = 0; q < 4; q++)
            hh[q] = __floats2half2_rn(fmaxf(a[2 * q], 0.f), fmaxf(a[2 * q + 1], 0.f));
        *(uint4*)&XsH[node_l * SA + j * 8] = *(uint4*)hh;
    } else {
        // zero pad so wmma reads are defined (row-independent anyway)
        uint4 z = {0, 0, 0, 0};
        *(uint4*)&XsH[node_l * SA + j * 8] = z;
    }
    __syncthreads();

    // 16 warps x 1 tile
    {
        int wp = tid >> 5;
        int tile_r = wp & 3, tile_c = wp >> 2;
        wmma::fragment<wmma::accumulator, 16, 16, 16, float> cf;
        wmma::fill_fragment(cf, 0.f);
        #pragma unroll
        for (int kk = 0; kk < 4; kk++) {
            wmma::fragment<wmma::matrix_a, 16, 16, 16, __half, wmma::row_major> af;
            wmma::fragment<wmma::matrix_b, 16, 16, 16, __half, wmma::row_major> bf;
            wmma::load_matrix_sync(af, XsH + tile_r * 16 * SA + kk * 16, SA);
            wmma::load_matrix_sync(bf, WsH + kk * 16 * SA + tile_c * 16, SA);
            wmma::mma_sync(cf, af, bf, cf);
        }
        wmma::store_matrix_sync(Cs + tile_r * 16 * SC + tile_c * 16, cf, SC, wmma::mem_row_major);
    }
    __syncthreads();

    if (node >= n) return;
    const float* crow = &Cs[node_l * SC + j * 8];
    __half2 hh[4];
    #pragma unroll
    for (int q = 0; q < 4; q++) hh[q] = __floats2half2_rn(crow[2 * q], crow[2 * q + 1]);
    *(uint4*)(xout + (size_t)node * 64 + j * 8) = *(uint4*)hh;
}

// -------------------- final: gather -> wmma MLP readout -> pooled mean --------------------
// 512 threads = 64 nodes x 8 threads
__global__ __launch_bounds__(512) void k_gather_readout(
    const float* __restrict__ bias,
    const float* __restrict__ Wr0, const float* __restrict__ br0,
    const float* __restrict__ Wr1, const float* __restrict__ br1,
    const int* __restrict__ batch, int n)
{
    __shared__ __half aggH[64 * SA];
    __shared__ __half W0H[64 * SB2];
    __shared__ float Cs[64 * SC2];
    __shared__ float W1s[32];
    __shared__ float b0s[32];

    int tid = threadIdx.x;
    // Wr0: 64x32 float -> half, stride SB2
    {
        const float4* W4 = (const float4*)Wr0;
        int idx = tid;                         // 512 float4s
        float4 f = W4[idx];
        int k = idx >> 3, c4 = idx & 7;
        __half2 h0 = __floats2half2_rn(f.x, f.y);
        __half2 h1 = __floats2half2_rn(f.z, f.w);
        uint2 u; u.x = *(unsigned*)&h0; u.y = *(unsigned*)&h1;
        *(uint2*)&W0H[k * SB2 + c4 * 4] = u;
    }
    if (tid < 32) { W1s[tid] = Wr1[tid]; b0s[tid] = br0[tid]; }

    int node_l = tid >> 3;
    int j = tid & 7;
    int node = blockIdx.x * 64 + node_l;
    bool valid = (node < n);

    if (valid) {
        float a[8];
        gather_core8(g_xwA, node, j, bias, a);   // no relu on last GNN layer
        __half2 hh[4];
        #pragma unroll
        for (int q = 0; q < 4; q++) hh[q] = __floats2half2_rn(a[2 * q], a[2 * q + 1]);
        *(uint4*)&aggH[node_l * SA + j * 8] = *(uint4*)hh;
    } else {
        uint4 z = {0, 0, 0, 0};
        *(uint4*)&aggH[node_l * SA + j * 8] = z;
    }
    __syncthreads();

    // 8 warps x 1 tile (64x32 output)
    {
        int wp = tid >> 5;
        if (wp < 8) {
            int tile_r = wp & 3, tile_c = wp >> 2;
            wmma::fragment<wmma::accumulator, 16, 16, 16, float> cf;
            wmma::fill_fragment(cf, 0.f);
            #pragma unroll
            for (int kk = 0; kk < 4; kk++) {
                wmma::fragment<wmma::matrix_a, 16, 16, 16, __half, wmma::row_major> af;
                wmma::fragment<wmma::matrix_b, 16, 16, 16, __half, wmma::row_major> bf;
                wmma::load_matrix_sync(af, aggH + tile_r * 16 * SA + kk * 16, SA);
                wmma::load_matrix_sync(bf, W0H + kk * 16 * SB2 + tile_c * 16, SB2);
                wmma::mma_sync(cf, af, bf, cf);
            }
            wmma::store_matrix_sync(Cs + tile_r * 16 * SC2 + tile_c * 16, cf, SC2, wmma::mem_row_major);
        }
    }
    __syncthreads();

    float s = 0.f, cv = 0.f;
    int g = -1;
    if (valid) {
        int c0 = j * 4;
        const float* crow = &Cs[node_l * SC2 + c0];
        const float4 w1 = *(const float4*)&W1s[c0];
        float a0 = crow[0] + b0s[c0 + 0];
        float a1 = crow[1] + b0s[c0 + 1];
        float a2 = crow[2] + b0s[c0 + 2];
        float a3 = crow[3] + b0s[c0 + 3];
        s = fmaxf(a0, 0.f) * w1.x + fmaxf(a1, 0.f) * w1.y
          + fmaxf(a2, 0.f) * w1.z + fmaxf(a3, 0.f) * w1.w;
        g = __ldg(batch + node);
    }

    const unsigned full = 0xffffffffu;
    s += __shfl_xor_sync(full, s, 4);
    s += __shfl_xor_sync(full, s, 2);
    s += __shfl_xor_sync(full, s, 1);

    if (valid && j == 0) { s += __ldg(br1); cv = 1.f; }
    else { s = 0.f; cv = 0.f; }

    int lane = tid & 31;
    #pragma unroll
    for (int off = 1; off < 32; off <<= 1) {
        float so = __shfl_up_sync(full, s, off);
        float co = __shfl_up_sync(full, cv, off);
        int go = __shfl_up_sync(full, g, off);
        if (lane >= off && go == g) { s += so; cv += co; }
    }
    int gn = __shfl_down_sync(full, g, 1);
    if ((lane == 31 || gn != g) && g >= 0) {
        atomicAdd(&g_sums[g], s);
        atomicAdd(&g_cnt[g], cv);
    }
}

// finalize output + reset accumulators/lookback for next launch
__global__ void k_finalize(float* __restrict__ out) {
    int g = threadIdx.x;
    out[g] = g_sums[g] / fmaxf(g_cnt[g], 1.0f);
    g_sums[g] = 0.f;
    g_cnt[g] = 0.f;
    if (g < 128) g_lbpack[g] = 0ull;
}

// -------------------- launch --------------------
extern "C" void kernel_launch(void* const* d_in, const int* in_sizes, int n_in,
                              void* d_out, int out_size)
{
    const float* x   = (const float*)d_in[0];
    const int*   ei  = (const int*)d_in[1];
    const float* ew  = (const float*)d_in[2];
    const int* batch = (const int*)d_in[3];
    const float* W0  = (const float*)d_in[4];
    const float* b0  = (const float*)d_in[5];
    const float* W1  = (const float*)d_in[6];
    const float* b1  = (const float*)d_in[7];
    const float* W2  = (const float*)d_in[8];
    const float* b2  = (const float*)d_in[9];
    const float* Wr0 = (const float*)d_in[10];
    const float* br0 = (const float*)d_in[11];
    const float* Wr1 = (const float*)d_in[12];
    const float* br1 = (const float*)d_in[13];
    float* out = (float*)d_out;

    int n = in_sizes[0] / HID;       // 100000
    int E = in_sizes[2];             // 1600000
    const int* src = ei;
    const int* dst = ei + E;

    int nb = (n + 1023) / 1024;      // 98 blocks: all resident -> lookback safe
    int gb = (n + 63) / 64;          // 1563 gemm/gather blocks
    int fb = (E + 255) / 256;        // 6250 fill blocks

    // launch #3 (0-indexed) is k_fused -> that's what ncu captures
    k_deg_hist<<<(E + 255) / 256, 256>>>(dst, ew, E);                   // 0
    k_scan<<<nb, 1024>>>(n, E);                                         // 1
    k_fill_gemm0<<<gb + fb, 256>>>(src, dst, ew, E, x, W0, n, gb);      // 2
    k_fused<<<gb, 512>>>(b0, W1, 1, n);                                 // 3  <- profiled
    k_fused<<<gb, 512>>>(b1, W2, 0, n);                                 // 4
    k_gather_readout<<<gb, 512>>>(b2, Wr0, br0, Wr1, br1, batch, n);    // 5
    k_finalize<<<1, 256>>>(out);                                        // 6
}

// round 13
// speedup vs baseline: 2.4931x; 1.1026x over previous
#include <cuda_runtime.h>
#include <cuda_fp16.h>
#include <mma.h>
using namespace nvcuda;

#define NN 100000
#define NE 1600000
#define NG 256
#define HID 64
#define NEP (NE + 3 * NN + 8)   // padded edge capacity + prefetch slack

// ---- static scratch (no allocations allowed) ----
__device__ __align__(16) __half g_xwA[NN * HID];
__device__ __align__(16) __half g_xwB[NN * HID];
__device__ unsigned long long g_packed[NN];        // [40:64)=count, [0:40)=sum(w) Q24
__device__ float g_deg[NN];                        // dinv = rsqrt(deg)
__device__ int   g_row[NN + 1];                    // padded CSR row offsets (by dst)
__device__ __align__(8) int2 g_nodeinfo[NN];       // (padded row offset, dinv-as-bits)
__device__ int   g_rank[NE];                       // per-edge rank within dst bucket
__device__ unsigned long long g_lbpack[128];       // lookback state
__device__ __align__(16) int2 g_edge[NEP];         // CSR record: (src<<7 byte-offset, norm-bits)
__device__ float g_sums[NG];
__device__ float g_cnt[NG];

#define Q24 16777216.0f

#define SA 72   // half matrix smem stride
#define SC 68   // float C smem stride
#define SB2 40  // readout B stride
#define SC2 36  // readout C stride

// -------------------- deg + hist + rank (one packed 64b atomic) --------------------
__global__ void k_deg_hist(const int* __restrict__ dst, const float* __restrict__ w, int E) {
    int e = blockIdx.x * blockDim.x + threadIdx.x;
    if (e < E) {
        int d = dst[e];
        unsigned long long add =
            (1ull << 40) | (unsigned long long)__float2uint_rn(w[e] * Q24);
        unsigned long long old = atomicAdd(&g_packed[d], add);
        g_rank[e] = (int)(old >> 40);
    }
}

// -------------------- single-pass decoupled-lookback scan (over PADDED counts) ------
// Also writes zero-norm pad records and re-zeroes g_packed for the next launch.
__global__ __launch_bounds__(1024) void k_scan(int n) {
    __shared__ int ws[32];
    __shared__ int prefix_s;
    int b = blockIdx.x, t = threadIdx.x;
    int i = b * 1024 + t;
    unsigned long long pk = (i < n) ? g_packed[i] : 0ull;
    int c = (int)(pk >> 40);
    int cpad = (c + 3) & ~3;                // pad bucket to multiple of 4 edges
    if (i < n) g_packed[i] = 0ull;          // reset for next launch

    const unsigned full = 0xffffffffu;
    int lane = t & 31, warp = t >> 5;
    int x = cpad;
    #pragma unroll
    for (int off = 1; off < 32; off <<= 1) {
        int y = __shfl_up_sync(full, x, off);
        if (lane >= off) x += y;
    }
    if (lane == 31) ws[warp] = x;
    __syncthreads();
    if (warp == 0) {
        int y = ws[lane];
        #pragma unroll
        for (int off = 1; off < 32; off <<= 1) {
            int z = __shfl_up_sync(full, y, off);
            if (lane >= off) y += z;
        }
        ws[lane] = y;
    }
    __syncthreads();
    int blockpref = (warp > 0) ? ws[warp - 1] : 0;
    int incl = x + blockpref;

    if (t == 1023) {
        unsigned long long p = (1ull << 32) | (unsigned)incl;
        *((volatile unsigned long long*)&g_lbpack[b]) = p;
    }
    if (t == 0) prefix_s = 0;
    __syncthreads();
    if (t < b) {
        unsigned long long p;
        do { p = *((volatile unsigned long long*)&g_lbpack[t]); } while (!(p >> 32));
        atomicAdd(&prefix_s, (int)(unsigned)p);
    }
    __syncthreads();

    int excl = incl - cpad + prefix_s;
    if (i < n) {
        g_row[i] = excl;
        float deg = 1.0f + (float)(pk & 0xFFFFFFFFFFull) * (1.0f / Q24);
        float dinv = rsqrtf(deg);
        g_deg[i] = dinv;
        int2 ni; ni.x = excl; ni.y = __float_as_int(dinv);
        g_nodeinfo[i] = ni;
        // zero-norm pad records (src-offset 0, norm 0.0): contribute exactly 0
        int2 z; z.x = 0; z.y = 0;
        for (int k = c; k < cpad; k++) g_edge[excl + k] = z;
    }
    if (i == n) g_row[n] = excl;            // total padded edge count
}

// -------------------- merged: CSR fill + layer-0 GEMM (wmma) --------------------
__global__ __launch_bounds__(256) void k_fill_gemm0(
    const int* __restrict__ src, const int* __restrict__ dst,
    const float* __restrict__ w, int E,
    const float* __restrict__ X, const float* __restrict__ W, int n,
    int gemm_blocks)
{
    __shared__ __half WsH[64 * SA];
    __shared__ __half XsH[64 * SA];
    __shared__ float Cs[64 * SC];

    int tid = threadIdx.x;

    if (blockIdx.x >= gemm_blocks) {
        // ---- fill part ----
        int e = (blockIdx.x - gemm_blocks) * 256 + tid;
        if (e < E) {
            int s = src[e], d = dst[e];
            int2 di = __ldg(g_nodeinfo + d);
            float nv = __ldg(g_deg + s) * w[e] * __int_as_float(di.y);
            int pos = di.x + g_rank[e];
            int2 rec; rec.x = s << 7; rec.y = __float_as_int(nv);   // byte offset
            g_edge[pos] = rec;
        }
        return;
    }

    // ---- gemm0: xwA = X @ W0 via wmma ----
    int row0 = blockIdx.x * 64;

    const float4* W4 = (const float4*)W;
    #pragma unroll
    for (int i = 0; i < 4; i++) {
        int idx = tid + 256 * i;
        float4 f = W4[idx];
        int k = idx >> 4, c4 = idx & 15;
        __half2 h0 = __floats2half2_rn(f.x, f.y);
        __half2 h1 = __floats2half2_rn(f.z, f.w);
        uint2 u; u.x = *(unsigned*)&h0; u.y = *(unsigned*)&h1;
        *(uint2*)&WsH[k * SA + c4 * 4] = u;
    }
    const float4* X4 = (const float4*)(X + (size_t)row0 * 64);
    #pragma unroll
    for (int i = 0; i < 4; i++) {
        int idx = tid + 256 * i;
        int r = idx >> 4, c4 = idx & 15;
        if (row0 + r < n) {
            float4 f = X4[idx];
            __half2 h0 = __floats2half2_rn(f.x, f.y);
            __half2 h1 = __floats2half2_rn(f.z, f.w);
            uint2 u; u.x = *(unsigned*)&h0; u.y = *(unsigned*)&h1;
            *(uint2*)&XsH[r * SA + c4 * 4] = u;
        }
    }
    __syncthreads();

    int wp = tid >> 5;
    int tile_r = wp & 3;
    #pragma unroll
    for (int t2 = 0; t2 < 2; t2++) {
        int tile_c = (wp >> 2) * 2 + t2;
        wmma::fragment<wmma::accumulator, 16, 16, 16, float> cf;
        wmma::fill_fragment(cf, 0.f);
        #pragma unroll
        for (int kk = 0; kk < 4; kk++) {
            wmma::fragment<wmma::matrix_a, 16, 16, 16, __half, wmma::row_major> af;
            wmma::fragment<wmma::matrix_b, 16, 16, 16, __half, wmma::row_major> bf;
            wmma::load_matrix_sync(af, XsH + tile_r * 16 * SA + kk * 16, SA);
            wmma::load_matrix_sync(bf, WsH + kk * 16 * SA + tile_c * 16, SA);
            wmma::mma_sync(cf, af, bf, cf);
        }
        wmma::store_matrix_sync(Cs + tile_r * 16 * SC + tile_c * 16, cf, SC, wmma::mem_row_major);
    }
    __syncthreads();

    int r = tid >> 2, c0 = (tid & 3) * 16;
    int row = row0 + r;
    if (row >= n) return;
    const float* crow = &Cs[r * SC + c0];
    __half2 hh[8];
    #pragma unroll
    for (int i = 0; i < 8; i++) hh[i] = __floats2half2_rn(crow[2 * i], crow[2 * i + 1]);
    uint4* dstp = (uint4*)(g_xwA + (size_t)row * 64 + c0);
    dstp[0] = ((uint4*)hh)[0];
    dstp[1] = ((uint4*)hh)[1];
}

// ---- gather core: 8 threads/node, 8 fp32 accumulators ----
// Padded buckets (multiple of 4 edges, 32B-aligned) -> guard-free pipelined loop
// with 2-records-per-LDG.128 and 32-bit byte-offset addressing.
#define ACC8v(v, nv) { const __half2* _h = (const __half2*)&(v); \
    float2 _t0 = __half22float2(_h[0]), _t1 = __half22float2(_h[1]); \
    float2 _t2 = __half22float2(_h[2]), _t3 = __half22float2(_h[3]); \
    a[0] += _t0.x * (nv); a[1] += _t0.y * (nv); \
    a[2] += _t1.x * (nv); a[3] += _t1.y * (nv); \
    a[4] += _t2.x * (nv); a[5] += _t2.y * (nv); \
    a[6] += _t3.x * (nv); a[7] += _t3.y * (nv); }

__device__ __forceinline__ void gather_core8(const __half* __restrict__ xwh,
                                             int node, int j,
                                             const float* __restrict__ bias,
                                             float* a /*[8]*/)
{
    int2 ni = __ldg(g_nodeinfo + node);      // (padded start, dinv)
    int start = ni.x;
    int end   = __ldg(g_row + node + 1);
    float dv = __int_as_float(ni.y);
    float inv = dv * dv;

    const char* base = (const char*)xwh + (j << 4);

    // bias + self-loop
    {
        uint4 v = __ldg((const uint4*)(base + ((unsigned)node << 7)));
        const float4* b4 = (const float4*)(bias + j * 8);
        float4 b0 = __ldg(b4), b1 = __ldg(b4 + 1);
        #pragma unroll
        for (int q = 0; q < 8; q++) a[q] = 0.f;
        ACC8v(v, inv);
        a[0] += b0.x; a[1] += b0.y; a[2] += b0.z; a[3] += b0.w;
        a[4] += b1.x; a[5] += b1.y; a[6] += b1.z; a[7] += b1.w;
    }

    const int4* ep = (const int4*)(g_edge + start);   // 2 records per int4
    int groups = (end - start) >> 2;                  // exact (padded)

    // prefetch first group (slack in g_edge makes this safe even if groups==0)
    int4 r01 = __ldg(ep);
    int4 r23 = __ldg(ep + 1);
    for (int gq = 0; gq < groups; gq++) {
        uint4 u0 = __ldg((const uint4*)(base + (unsigned)r01.x));
        uint4 u1 = __ldg((const uint4*)(base + (unsigned)r01.z));
        uint4 u2 = __ldg((const uint4*)(base + (unsigned)r23.x));
        uint4 u3 = __ldg((const uint4*)(base + (unsigned)r23.z));
        float n0 = __int_as_float(r01.y), n1 = __int_as_float(r01.w);
        float n2 = __int_as_float(r23.y), n3 = __int_as_float(r23.w);
        // prefetch next group's records while features are in flight
        int4 q01 = __ldg(ep + 2 * gq + 2);
        int4 q23 = __ldg(ep + 2 * gq + 3);
        ACC8v(u0, n0); ACC8v(u1, n1); ACC8v(u2, n2); ACC8v(u3, n3);
        r01 = q01; r23 = q23;
    }
}

// -------------------- fused: gather -> relu(fp16 smem) -> wmma @W -> xw out ----------
__global__ __launch_bounds__(512, 3) void k_fused(
    const float* __restrict__ bias, const float* __restrict__ W,
    int in_is_A, int n)
{
    __shared__ __half WsH[64 * SA];
    __shared__ __half XsH[64 * SA];
    __shared__ float Cs[64 * SC];

    const __half* xin = in_is_A ? g_xwA : g_xwB;
    __half* xout      = in_is_A ? g_xwB : g_xwA;

    int tid = threadIdx.x;
    int row0 = blockIdx.x * 64;

    const float4* W4 = (const float4*)W;
    #pragma unroll
    for (int i = 0; i < 2; i++) {
        int idx = tid + 512 * i;
        float4 f = W4[idx];
        int k = idx >> 4, c4 = idx & 15;
        __half2 h0 = __floats2half2_rn(f.x, f.y);
        __half2 h1 = __floats2half2_rn(f.z, f.w);
        uint2 u; u.x = *(unsigned*)&h0; u.y = *(unsigned*)&h1;
        *(uint2*)&WsH[k * SA + c4 * 4] = u;
    }

    int node_l = tid >> 3;
    int j = tid & 7;
    int node = row0 + node_l;

    if (node < n) {
        float a[8];
        gather_core8(xin, node, j, bias, a);
        __half2 hh[4];
        #pragma unroll
        for (int q = 0; q < 4; q++)
            hh[q] = __floats2half2_rn(fmaxf(a[2 * q], 0.f), fmaxf(a[2 * q + 1], 0.f));
        *(uint4*)&XsH[node_l * SA + j * 8] = *(uint4*)hh;
    } else {
        uint4 z = {0, 0, 0, 0};
        *(uint4*)&XsH[node_l * SA + j * 8] = z;
    }
    __syncthreads();

    {
        int wp = tid >> 5;
        int tile_r = wp & 3, tile_c = wp >> 2;
        wmma::fragment<wmma::accumulator, 16, 16, 16, float> cf;
        wmma::fill_fragment(cf, 0.f);
        #pragma unroll
        for (int kk = 0; kk < 4; kk++) {
            wmma::fragment<wmma::matrix_a, 16, 16, 16, __half, wmma::row_major> af;
            wmma::fragment<wmma::matrix_b, 16, 16, 16, __half, wmma::row_major> bf;
            wmma::load_matrix_sync(af, XsH + tile_r * 16 * SA + kk * 16, SA);
            wmma::load_matrix_sync(bf, WsH + kk * 16 * SA + tile_c * 16, SA);
            wmma::mma_sync(cf, af, bf, cf);
        }
        wmma::store_matrix_sync(Cs + tile_r * 16 * SC + tile_c * 16, cf, SC, wmma::mem_row_major);
    }
    __syncthreads();

    if (node >= n) return;
    const float* crow = &Cs[node_l * SC + j * 8];
    __half2 hh[4];
    #pragma unroll
    for (int q = 0; q < 4; q++) hh[q] = __floats2half2_rn(crow[2 * q], crow[2 * q + 1]);
    *(uint4*)(xout + (size_t)node * 64 + j * 8) = *(uint4*)hh;
}

// -------------------- final: gather -> wmma MLP readout -> pooled mean --------------
__global__ __launch_bounds__(512, 3) void k_gather_readout(
    const float* __restrict__ bias,
    const float* __restrict__ Wr0, const float* __restrict__ br0,
    const float* __restrict__ Wr1, const float* __restrict__ br1,
    const int* __restrict__ batch, int n)
{
    __shared__ __half aggH[64 * SA];
    __shared__ __half W0H[64 * SB2];
    __shared__ float Cs[64 * SC2];
    __shared__ float W1s[32];
    __shared__ float b0s[32];

    int tid = threadIdx.x;
    {
        const float4* W4 = (const float4*)Wr0;
        float4 f = W4[tid];
        int k = tid >> 3, c4 = tid & 7;
        __half2 h0 = __floats2half2_rn(f.x, f.y);
        __half2 h1 = __floats2half2_rn(f.z, f.w);
        uint2 u; u.x = *(unsigned*)&h0; u.y = *(unsigned*)&h1;
        *(uint2*)&W0H[k * SB2 + c4 * 4] = u;
    }
    if (tid < 32) { W1s[tid] = Wr1[tid]; b0s[tid] = br0[tid]; }

    int node_l = tid >> 3;
    int j = tid & 7;
    int node = blockIdx.x * 64 + node_l;
    bool valid = (node < n);

    if (valid) {
        float a[8];
        gather_core8(g_xwA, node, j, bias, a);   // no relu on last GNN layer
        __half2 hh[4];
        #pragma unroll
        for (int q = 0; q < 4; q++) hh[q] = __floats2half2_rn(a[2 * q], a[2 * q + 1]);
        *(uint4*)&aggH[node_l * SA + j * 8] = *(uint4*)hh;
    } else {
        uint4 z = {0, 0, 0, 0};
        *(uint4*)&aggH[node_l * SA + j * 8] = z;
    }
    __syncthreads();

    {
        int wp = tid >> 5;
        if (wp < 8) {
            int tile_r = wp & 3, tile_c = wp >> 2;
            wmma::fragment<wmma::accumulator, 16, 16, 16, float> cf;
            wmma::fill_fragment(cf, 0.f);
            #pragma unroll
            for (int kk = 0; kk < 4; kk++) {
                wmma::fragment<wmma::matrix_a, 16, 16, 16, __half, wmma::row_major> af;
                wmma::fragment<wmma::matrix_b, 16, 16, 16, __half, wmma::row_major> bf;
                wmma::load_matrix_sync(af, aggH + tile_r * 16 * SA + kk * 16, SA);
                wmma::load_matrix_sync(bf, W0H + kk * 16 * SB2 + tile_c * 16, SB2);
                wmma::mma_sync(cf, af, bf, cf);
            }
            wmma::store_matrix_sync(Cs + tile_r * 16 * SC2 + tile_c * 16, cf, SC2, wmma::mem_row_major);
        }
    }
    __syncthreads();

    float s = 0.f, cv = 0.f;
    int g = -1;
    if (valid) {
        int c0 = j * 4;
        const float* crow = &Cs[node_l * SC2 + c0];
        const float4 w1 = *(const float4*)&W1s[c0];
        float a0 = crow[0] + b0s[c0 + 0];
        float a1 = crow[1] + b0s[c0 + 1];
        float a2 = crow[2] + b0s[c0 + 2];
        float a3 = crow[3] + b0s[c0 + 3];
        s = fmaxf(a0, 0.f) * w1.x + fmaxf(a1, 0.f) * w1.y
          + fmaxf(a2, 0.f) * w1.z + fmaxf(a3, 0.f) * w1.w;
        g = __ldg(batch + node);
    }

    const unsigned full = 0xffffffffu;
    s += __shfl_xor_sync(full, s, 4);
    s += __shfl_xor_sync(full, s, 2);
    s += __shfl_xor_sync(full, s, 1);

    if (valid && j == 0) { s += __ldg(br1); cv = 1.f; }
    else { s = 0.f; cv = 0.f; }

    int lane = tid & 31;
    #pragma unroll
    for (int off = 1; off < 32; off <<= 1) {
        float so = __shfl_up_sync(full, s, off);
        float co = __shfl_up_sync(full, cv, off);
        int go = __shfl_up_sync(full, g, off);
        if (lane >= off && go == g) { s += so; cv += co; }
    }
    int gn = __shfl_down_sync(full, g, 1);
    if ((lane == 31 || gn != g) && g >= 0) {
        atomicAdd(&g_sums[g], s);
        atomicAdd(&g_cnt[g], cv);
    }
}

// finalize output + reset accumulators/lookback for next launch
__global__ void k_finalize(float* __restrict__ out) {
    int g = threadIdx.x;
    out[g] = g_sums[g] / fmaxf(g_cnt[g], 1.0f);
    g_sums[g] = 0.f;
    g_cnt[g] = 0.f;
    if (g < 128) g_lbpack[g] = 0ull;
}

// -------------------- launch --------------------
extern "C" void kernel_launch(void* const* d_in, const int* in_sizes, int n_in,
                              void* d_out, int out_size)
{
    const float* x   = (const float*)d_in[0];
    const int*   ei  = (const int*)d_in[1];
    const float* ew  = (const float*)d_in[2];
    const int* batch = (const int*)d_in[3];
    const float* W0  = (const float*)d_in[4];
    const float* b0  = (const float*)d_in[5];
    const float* W1  = (const float*)d_in[6];
    const float* b1  = (const float*)d_in[7];
    const float* W2  = (const float*)d_in[8];
    const float* b2  = (const float*)d_in[9];
    const float* Wr0 = (const float*)d_in[10];
    const float* br0 = (const float*)d_in[11];
    const float* Wr1 = (const float*)d_in[12];
    const float* br1 = (const float*)d_in[13];
    float* out = (float*)d_out;

    int n = in_sizes[0] / HID;       // 100000
    int E = in_sizes[2];             // 1600000
    const int* src = ei;
    const int* dst = ei + E;

    int nb = (n + 1023) / 1024;      // 98 blocks: all resident -> lookback safe
    int gb = (n + 63) / 64;          // 1563 gemm/gather blocks
    int fb = (E + 255) / 256;        // 6250 fill blocks

    // launch #3 (0-indexed) is k_fused -> that's what ncu captures
    k_deg_hist<<<(E + 255) / 256, 256>>>(dst, ew, E);                   // 0
    k_scan<<<nb, 1024>>>(n);                                            // 1
    k_fill_gemm0<<<gb + fb, 256>>>(src, dst, ew, E, x, W0, n, gb);      // 2
    k_fused<<<gb, 512>>>(b0, W1, 1, n);                                 // 3  <- profiled
    k_fused<<<gb, 512>>>(b1, W2, 0, n);                                 // 4
    k_gather_readout<<<gb, 512>>>(b2, Wr0, br0, Wr1, br1, batch, n);    // 5
    k_finalize<<<1, 256>>>(out);                                        // 6
}